// round 9
// baseline (speedup 1.0000x reference)
#include <cuda_runtime.h>
#include <cuda_bf16.h>

#define DIMB    25
#define NNODES  20000
#define NEDGES  320000
#define NFEAT   300
#define NHID    64
#define NCLASS  50

#define K1   NFEAT            // 300
#define N1   (DIMB*NHID)      // 1600
#define K2   N1               // 1600
#define N2R  (DIMB*NCLASS)    // 1250 (real)
#define N2   1280             // padded to multiple of 128

// ---------------- scratch (device globals; zero-initialized bss) ----------------
__device__ float g_W1t[K1 * N1];        // [300][1600]  W1t[f][d*64+h]
__device__ float g_W2t[K2 * N2];        // [1600][1280] W2t[k][d*50+c]; cols>=1250 stay 0
__device__ float g_sup1[(size_t)NNODES * N1];   // [20000][1600]
__device__ float g_h1  [(size_t)NNODES * N1];   // h1cat layout [n][d*64+h]
__device__ float g_sup2[(size_t)NNODES * N2];   // [20000][1280]
__device__ float g_acc2[(size_t)NNODES * N2];   // scatter target layer 2

// ---------------- vector global reductions (sm_90+) ----------------
__device__ __forceinline__ void red_add_v4(float* addr, float a, float b, float c, float d) {
    asm volatile("red.global.add.v4.f32 [%0], {%1, %2, %3, %4};"
                 :: "l"(addr), "f"(a), "f"(b), "f"(c), "f"(d) : "memory");
}
__device__ __forceinline__ void red_add_v2(float* addr, float a, float b) {
    asm volatile("red.global.add.v2.f32 [%0], {%1, %2};"
                 :: "l"(addr), "f"(a), "f"(b) : "memory");
}

// ---------------- weight repacks ----------------
__global__ void repack_w1(const float* __restrict__ W1) {
    int i = blockIdx.x * blockDim.x + threadIdx.x;   // over K1*N1
    if (i >= K1 * N1) return;
    int f = i / N1, j = i - f * N1;
    int d = j >> 6, h = j & 63;
    g_W1t[i] = W1[((size_t)d * NFEAT + f) * NHID + h];
}

__global__ void repack_w2(const float* __restrict__ W2) {
    int i = blockIdx.x * blockDim.x + threadIdx.x;   // over K2*N2R
    if (i >= K2 * N2R) return;
    int k = i / N2R, j = i - k * N2R;
    int d = j / NCLASS, c = j - d * NCLASS;
    g_W2t[(size_t)k * N2 + j] = W2[((size_t)d * K2 + k) * NCLASS + c];
}

// ---------------- double-buffered tiled SGEMM: C[M,N] = A[M,K] @ B[K,N] ----
// 128x128 tile, BK=8, 256 threads, 8x8 micro-tile per thread, 2-stage smem.
__device__ __forceinline__ void gemm_body(
    const float* __restrict__ A, const float* __restrict__ B, float* __restrict__ C,
    int M, int N, int K, int lda, int ldb, int ldc)
{
    const int BM = 128, BN = 128, BK = 8, TM = 8, TN = 8;
    __shared__ float As[2][BK][BM];
    __shared__ float Bs[2][BK][BN];

    int tid = threadIdx.x;            // 0..255
    int tx = tid & 15;                // 16 cols of threads
    int ty = tid >> 4;                // 16 rows of threads
    int rowBase = blockIdx.y * BM;
    int colBase = blockIdx.x * BN;

    float acc[TM][TN];
    #pragma unroll
    for (int i = 0; i < TM; i++)
        #pragma unroll
        for (int j = 0; j < TN; j++) acc[i][j] = 0.f;

    // A-load: each thread loads 4 consecutive k's of one row
    int aRow = tid >> 1;              // 0..127
    int aCol = (tid & 1) * 4;         // 0 or 4
    int gRow = rowBase + aRow;
    // B-load: each thread loads float4 along N
    int bRow = tid >> 5;              // 0..7
    int bCol = (tid & 31) * 4;        // 0..124
    int gColB = colBase + bCol;

    const int nIter = (K + BK - 1) / BK;

    // ---- load tile 0 into buffer 0 ----
    {
        #pragma unroll
        for (int i = 0; i < 4; i++) {
            int gk = aCol + i;
            As[0][aCol + i][aRow] = (gRow < M && gk < K) ? A[(size_t)gRow * lda + gk] : 0.f;
        }
        float4 bv = make_float4(0.f, 0.f, 0.f, 0.f);
        if (bRow < K && gColB < N)
            bv = *reinterpret_cast<const float4*>(&B[(size_t)bRow * ldb + gColB]);
        *reinterpret_cast<float4*>(&Bs[0][bRow][bCol]) = bv;
    }
    __syncthreads();

    int buf = 0;
    for (int it = 0; it < nIter; ++it) {
        // ---- prefetch tile it+1 into registers (overlaps with compute) ----
        float a_pref[4];
        float4 b_pref = make_float4(0.f, 0.f, 0.f, 0.f);
        bool have_next = (it + 1) < nIter;
        if (have_next) {
            int k0n = (it + 1) * BK;
            #pragma unroll
            for (int i = 0; i < 4; i++) {
                int gk = k0n + aCol + i;
                a_pref[i] = (gRow < M && gk < K) ? A[(size_t)gRow * lda + gk] : 0.f;
            }
            int gk = k0n + bRow;
            if (gk < K && gColB < N)
                b_pref = *reinterpret_cast<const float4*>(&B[(size_t)gk * ldb + gColB]);
        }

        // ---- compute on current buffer ----
        #pragma unroll
        for (int kk = 0; kk < BK; kk++) {
            float4 ra0 = *reinterpret_cast<const float4*>(&As[buf][kk][ty * TM]);
            float4 ra1 = *reinterpret_cast<const float4*>(&As[buf][kk][ty * TM + 4]);
            float4 rb0 = *reinterpret_cast<const float4*>(&Bs[buf][kk][tx * TN]);
            float4 rb1 = *reinterpret_cast<const float4*>(&Bs[buf][kk][tx * TN + 4]);
            float ra[TM] = {ra0.x, ra0.y, ra0.z, ra0.w, ra1.x, ra1.y, ra1.z, ra1.w};
            float rb[TN] = {rb0.x, rb0.y, rb0.z, rb0.w, rb1.x, rb1.y, rb1.z, rb1.w};
            #pragma unroll
            for (int i = 0; i < TM; i++)
                #pragma unroll
                for (int j = 0; j < TN; j++)
                    acc[i][j] += ra[i] * rb[j];
        }

        // ---- commit prefetched tile to the other buffer ----
        if (have_next) {
            int nbuf = buf ^ 1;
            #pragma unroll
            for (int i = 0; i < 4; i++)
                As[nbuf][aCol + i][aRow] = a_pref[i];
            *reinterpret_cast<float4*>(&Bs[nbuf][bRow][bCol]) = b_pref;
        }
        __syncthreads();
        buf ^= 1;
    }

    #pragma unroll
    for (int i = 0; i < TM; i++) {
        int r = rowBase + ty * TM + i;
        if (r >= M) continue;
        #pragma unroll
        for (int j = 0; j < TN; j++) {
            int cl = colBase + tx * TN + j;
            if (cl < N) C[(size_t)r * ldc + cl] = acc[i][j];
        }
    }
}

__global__ __launch_bounds__(256) void gemm1_kernel(const float* __restrict__ x) {
    gemm_body(x, g_W1t, g_sup1, NNODES, N1, K1, K1, N1, N1);
}
__global__ __launch_bounds__(256) void gemm2_kernel() {
    gemm_body(g_h1, g_W2t, g_sup2, NNODES, N2, K2, K2, N2, N2);
}

// ---------------- bias init / relu / scatter / pool ----------------
__global__ void init_h1(const float* __restrict__ b1) {
    unsigned i = blockIdx.x * blockDim.x + threadIdx.x;
    if (i >= (unsigned)(NNODES) * N1) return;
    unsigned j = i % N1;
    g_h1[i] = b1[j];     // b1 flat index d*64+h == j
}

__global__ void scatter1(const int* __restrict__ rows, const int* __restrict__ cols,
                         const float* __restrict__ vals) {
    unsigned i = blockIdx.x * blockDim.x + threadIdx.x;
    const unsigned total = (unsigned)DIMB * NEDGES * 16;  // 16 float4 groups / edge: 128M
    if (i >= total) return;
    unsigned g  = i & 15u;
    unsigned el = i >> 4;                 // d*NEDGES + e  (warp-uniform pairs)
    unsigned d  = el / NEDGES;            // mul-shift
    int r  = rows[el];
    int c  = cols[el];
    float v = vals[el];
    const float4 s = *reinterpret_cast<const float4*>(
        &g_sup1[(size_t)c * N1 + d * NHID + g * 4]);
    float* dst = &g_h1[(size_t)r * N1 + d * NHID + g * 4];
    red_add_v4(dst, v * s.x, v * s.y, v * s.z, v * s.w);
}

__global__ void relu_h1() {
    unsigned i = (blockIdx.x * blockDim.x + threadIdx.x) * 4;
    if (i >= (unsigned)NNODES * N1) return;
    float4* p = reinterpret_cast<float4*>(&g_h1[i]);
    float4 v = *p;
    v.x = fmaxf(v.x, 0.f); v.y = fmaxf(v.y, 0.f);
    v.z = fmaxf(v.z, 0.f); v.w = fmaxf(v.w, 0.f);
    *p = v;
}

__global__ void init_acc2(const float* __restrict__ b2) {
    unsigned i = blockIdx.x * blockDim.x + threadIdx.x;
    if (i >= (unsigned)NNODES * N2R) return;
    unsigned n = i / N2R;
    unsigned j = i - n * N2R;
    g_acc2[(size_t)n * N2 + j] = b2[j];    // b2 flat index d*50+c == j
}

__global__ void scatter2(const int* __restrict__ rows, const int* __restrict__ cols,
                         const float* __restrict__ vals) {
    unsigned i = blockIdx.x * blockDim.x + threadIdx.x;
    const unsigned total = (unsigned)DIMB * NEDGES * 32;  // 25 float2 groups, padded to 32: 256M
    if (i >= total) return;
    unsigned g = i & 31u;
    if (g >= 25u) return;
    unsigned el = i >> 5;                 // warp-uniform: one edge per warp
    unsigned d  = el / NEDGES;
    int r  = rows[el];
    int c  = cols[el];
    float v = vals[el];
    const float2 s = *reinterpret_cast<const float2*>(
        &g_sup2[(size_t)c * N2 + d * NCLASS + g * 2]);
    red_add_v2(&g_acc2[(size_t)r * N2 + d * NCLASS + g * 2], v * s.x, v * s.y);
}

__global__ void maxpool(float* __restrict__ out) {
    int i = blockIdx.x * blockDim.x + threadIdx.x;   // over NNODES*NCLASS
    if (i >= NNODES * NCLASS) return;
    int n = i / NCLASS, c = i - n * NCLASS;
    float m = 0.f;                                   // relu floor
    #pragma unroll
    for (int d = 0; d < DIMB; d++)
        m = fmaxf(m, g_acc2[(size_t)n * N2 + d * NCLASS + c]);
    out[i] = m;
}

// ---------------- launch ----------------
extern "C" void kernel_launch(void* const* d_in, const int* in_sizes, int n_in,
                              void* d_out, int out_size) {
    const float* x    = (const float*)d_in[0];
    const int*   rows = (const int*)  d_in[1];
    const int*   cols = (const int*)  d_in[2];
    const float* vals = (const float*)d_in[3];
    const float* W1   = (const float*)d_in[4];
    const float* b1   = (const float*)d_in[5];
    const float* W2   = (const float*)d_in[6];
    const float* b2   = (const float*)d_in[7];
    float* out = (float*)d_out;

    // weight repacks
    repack_w1<<<(K1 * N1 + 255) / 256, 256>>>(W1);
    repack_w2<<<(K2 * N2R + 255) / 256, 256>>>(W2);

    // layer 1: sup1 = x @ W1cat
    dim3 g1((N1 + 127) / 128, (NNODES + 127) / 128);
    gemm1_kernel<<<g1, 256>>>(x);

    // h1 = relu(spmm(sup1) + b1)
    {
        unsigned tot = (unsigned)NNODES * N1;
        init_h1<<<(tot + 255) / 256, 256>>>(b1);
        unsigned stot = (unsigned)DIMB * NEDGES * 16;
        scatter1<<<(stot + 255) / 256, 256>>>(rows, cols, vals);
        relu_h1<<<(tot / 4 + 255) / 256, 256>>>();
    }

    // layer 2: sup2 = h1cat @ W2cat
    dim3 g2((N2 + 127) / 128, (NNODES + 127) / 128);
    gemm2_kernel<<<g2, 256>>>();

    // acc2 = spmm(sup2) + b2 ; out = max_d relu(acc2)
    {
        unsigned tot = (unsigned)NNODES * N2R;
        init_acc2<<<(tot + 255) / 256, 256>>>(b2);
        unsigned stot = (unsigned)DIMB * NEDGES * 32;
        scatter2<<<(stot + 255) / 256, 256>>>(rows, cols, vals);
        maxpool<<<(NNODES * NCLASS + 255) / 256, 256>>>(out);
    }
}

// round 15
// speedup vs baseline: 1.8887x; 1.8887x over previous
#include <cuda_runtime.h>
#include <cuda_bf16.h>

#define DIMB    25
#define NNODES  20000
#define NEDGES  320000
#define NFEAT   300
#define NHID    64
#define NCLASS  50

#define K1   NFEAT            // 300
#define K1P  320              // K1 padded to multiple of 32
#define N1   (DIMB*NHID)      // 1600
#define K2   N1               // 1600
#define N2R  (DIMB*NCLASS)    // 1250 (real)
#define N2   1280             // padded to multiple of 128

// ---------------- scratch (device globals; zero-initialized bss) ----------------
__device__ float g_sup1[(size_t)NNODES * N1];   // [20000][1600]
__device__ float g_h1  [(size_t)NNODES * N1];   // h1cat fp32 (scatter target)
__device__ float g_sup2[(size_t)NNODES * N2];   // [20000][1280]
__device__ float g_acc2[(size_t)NNODES * N2];   // scatter target layer 2

// bf16 split operands (2-term: hi + lo residual). Unwritten pad regions stay 0.
__device__ __nv_bfloat16 g_xh[(size_t)NNODES * K1P];
__device__ __nv_bfloat16 g_xl[(size_t)NNODES * K1P];
__device__ __nv_bfloat16 g_W1h[K1P * N1];
__device__ __nv_bfloat16 g_W1l[K1P * N1];
__device__ __nv_bfloat16 g_h1h[(size_t)NNODES * K2];
__device__ __nv_bfloat16 g_h1l[(size_t)NNODES * K2];
__device__ __nv_bfloat16 g_W2h[K2 * N2];
__device__ __nv_bfloat16 g_W2l[K2 * N2];

// ---------------- vector global reductions (sm_90+) ----------------
__device__ __forceinline__ void red_add_v4(float* addr, float a, float b, float c, float d) {
    asm volatile("red.global.add.v4.f32 [%0], {%1, %2, %3, %4};"
                 :: "l"(addr), "f"(a), "f"(b), "f"(c), "f"(d) : "memory");
}
__device__ __forceinline__ void red_add_v2(float* addr, float a, float b) {
    asm volatile("red.global.add.v2.f32 [%0], {%1, %2};"
                 :: "l"(addr), "f"(a), "f"(b) : "memory");
}

// ---------------- mma helpers ----------------
__device__ __forceinline__ unsigned su32(const void* p) {
    return (unsigned)__cvta_generic_to_shared(p);
}
__device__ __forceinline__ void ldsm4(unsigned a, unsigned r[4]) {
    asm volatile("ldmatrix.sync.aligned.m8n8.x4.shared.b16 {%0,%1,%2,%3},[%4];"
                 : "=r"(r[0]), "=r"(r[1]), "=r"(r[2]), "=r"(r[3]) : "r"(a));
}
__device__ __forceinline__ void ldsm4t(unsigned a, unsigned r[4]) {
    asm volatile("ldmatrix.sync.aligned.m8n8.x4.trans.shared.b16 {%0,%1,%2,%3},[%4];"
                 : "=r"(r[0]), "=r"(r[1]), "=r"(r[2]), "=r"(r[3]) : "r"(a));
}
__device__ __forceinline__ void mma16816(float d[4], const unsigned a[4],
                                         unsigned b0, unsigned b1) {
    asm volatile(
        "mma.sync.aligned.m16n8k16.row.col.f32.bf16.bf16.f32 "
        "{%0,%1,%2,%3},{%4,%5,%6,%7},{%8,%9},{%0,%1,%2,%3};"
        : "+f"(d[0]), "+f"(d[1]), "+f"(d[2]), "+f"(d[3])
        : "r"(a[0]), "r"(a[1]), "r"(a[2]), "r"(a[3]), "r"(b0), "r"(b1));
}
__device__ __forceinline__ void split2(float v, __nv_bfloat16& h, __nv_bfloat16& l) {
    h = __float2bfloat16(v);
    l = __float2bfloat16(v - __bfloat162float(h));
}

// ---------------- split / repack kernels ----------------
__global__ void split_x(const float* __restrict__ x) {
    int i = blockIdx.x * blockDim.x + threadIdx.x;  // over NNODES*K1
    if (i >= NNODES * K1) return;
    int n = i / K1, f = i - n * K1;
    __nv_bfloat16 h, l;
    split2(x[i], h, l);
    g_xh[(size_t)n * K1P + f] = h;
    g_xl[(size_t)n * K1P + f] = l;
}

__global__ void repack_split_w1(const float* __restrict__ W1) {
    int i = blockIdx.x * blockDim.x + threadIdx.x;  // over K1*N1
    if (i >= K1 * N1) return;
    int f = i / N1, j = i - f * N1;
    int d = j >> 6, h = j & 63;
    __nv_bfloat16 bh, bl;
    split2(W1[((size_t)d * NFEAT + f) * NHID + h], bh, bl);
    g_W1h[i] = bh;   // row f, col j  (f*N1 + j == i)
    g_W1l[i] = bl;
}

__global__ void repack_split_w2(const float* __restrict__ W2) {
    int i = blockIdx.x * blockDim.x + threadIdx.x;  // over K2*N2R
    if (i >= K2 * N2R) return;
    int k = i / N2R, j = i - k * N2R;
    int d = j / NCLASS, c = j - d * NCLASS;
    __nv_bfloat16 bh, bl;
    split2(W2[((size_t)d * K2 + k) * NCLASS + c], bh, bl);
    g_W2h[(size_t)k * N2 + j] = bh;
    g_W2l[(size_t)k * N2 + j] = bl;
}

// ---------------- bf16-split tensor-core GEMM ----------------
// C[M,N] = A[M,K] @ B[K,N], fp32 via Ah*Bh + Ah*Bl + Al*Bh (fp32 accum).
// 128x128 CTA tile, BK=32, 256 threads (8 warps: 4x2, 32x64 warp tile).
__global__ __launch_bounds__(256) void mma_gemm(
    const __nv_bfloat16* __restrict__ Ah, const __nv_bfloat16* __restrict__ Al,
    const __nv_bfloat16* __restrict__ Bh, const __nv_bfloat16* __restrict__ Bl,
    float* __restrict__ C, int M, int N, int K)
{
    __shared__ __align__(16) __nv_bfloat16 As[2][128][40];   // stride 40: conflict-free ldsm
    __shared__ __align__(16) __nv_bfloat16 Bs[2][32][136];   // stride 136: conflict-free ldsm.trans

    const int tid  = threadIdx.x;
    const int lane = tid & 31;
    const int wid  = tid >> 5;
    const int wm   = wid >> 1;       // 0..3 -> rows wm*32
    const int wn   = wid & 1;        // 0..1 -> cols wn*64
    const int rowBase = blockIdx.y * 128;
    const int colBase = blockIdx.x * 128;

    float acc[2][8][4];
    #pragma unroll
    for (int a = 0; a < 2; a++)
        #pragma unroll
        for (int b = 0; b < 8; b++)
            #pragma unroll
            for (int c = 0; c < 4; c++) acc[a][b][c] = 0.f;

    const int ar = tid >> 2;            // 0..63 (A row slot)
    const int aseg = (tid & 3) * 8;     // 8-bf16 segment within BK=32
    const int br = tid >> 4;            // 0..15 (B k-row slot)
    const int bseg = (tid & 15) * 8;    // 8-bf16 segment within BN=128

    for (int k0 = 0; k0 < K; k0 += 32) {
        // ---- load A chunk (128x32 hi+lo) ----
        #pragma unroll
        for (int rr = 0; rr < 2; rr++) {
            int r = ar + rr * 64;
            int gr = rowBase + r;
            uint4 vh = make_uint4(0, 0, 0, 0), vl = make_uint4(0, 0, 0, 0);
            if (gr < M) {
                vh = *reinterpret_cast<const uint4*>(&Ah[(size_t)gr * K + k0 + aseg]);
                vl = *reinterpret_cast<const uint4*>(&Al[(size_t)gr * K + k0 + aseg]);
            }
            *reinterpret_cast<uint4*>(&As[0][r][aseg]) = vh;
            *reinterpret_cast<uint4*>(&As[1][r][aseg]) = vl;
        }
        // ---- load B chunk (32x128 hi+lo) ----
        #pragma unroll
        for (int rr = 0; rr < 2; rr++) {
            int r = br + rr * 16;
            int gc = colBase + bseg;
            uint4 vh = make_uint4(0, 0, 0, 0), vl = make_uint4(0, 0, 0, 0);
            if (gc < N) {
                vh = *reinterpret_cast<const uint4*>(&Bh[(size_t)(k0 + r) * N + gc]);
                vl = *reinterpret_cast<const uint4*>(&Bl[(size_t)(k0 + r) * N + gc]);
            }
            *reinterpret_cast<uint4*>(&Bs[0][r][bseg]) = vh;
            *reinterpret_cast<uint4*>(&Bs[1][r][bseg]) = vl;
        }
        __syncthreads();

        #pragma unroll
        for (int ks = 0; ks < 2; ks++) {
            const int kl = ks * 16;
            unsigned ah[2][4], al[2][4];
            #pragma unroll
            for (int mt = 0; mt < 2; mt++) {
                int rowS = wm * 32 + mt * 16 + (lane & 15);
                int colS = kl + (lane >> 4) * 8;
                ldsm4(su32(&As[0][rowS][colS]), ah[mt]);
                ldsm4(su32(&As[1][rowS][colS]), al[mt]);
            }
            unsigned bh[4][4], bl[4][4];
            #pragma unroll
            for (int t = 0; t < 4; t++) {
                int rowS = kl + ((lane >> 3) & 1) * 8 + (lane & 7);
                int colS = wn * 64 + t * 16 + (lane >> 4) * 8;
                ldsm4t(su32(&Bs[0][rowS][colS]), bh[t]);
                ldsm4t(su32(&Bs[1][rowS][colS]), bl[t]);
            }
            #pragma unroll
            for (int mt = 0; mt < 2; mt++)
                #pragma unroll
                for (int nt = 0; nt < 8; nt++) {
                    int t = nt >> 1, p = (nt & 1) * 2;
                    mma16816(acc[mt][nt], ah[mt], bh[t][p], bh[t][p + 1]);
                    mma16816(acc[mt][nt], ah[mt], bl[t][p], bl[t][p + 1]);
                    mma16816(acc[mt][nt], al[mt], bh[t][p], bh[t][p + 1]);
                }
        }
        __syncthreads();
    }

    // ---- epilogue ----
    #pragma unroll
    for (int mt = 0; mt < 2; mt++) {
        #pragma unroll
        for (int nt = 0; nt < 8; nt++) {
            int row0 = rowBase + wm * 32 + mt * 16 + (lane >> 2);
            int col0 = colBase + wn * 64 + nt * 8 + (lane & 3) * 2;
            if (col0 < N) {
                if (row0 < M)
                    *reinterpret_cast<float2*>(&C[(size_t)row0 * N + col0]) =
                        make_float2(acc[mt][nt][0], acc[mt][nt][1]);
                if (row0 + 8 < M)
                    *reinterpret_cast<float2*>(&C[(size_t)(row0 + 8) * N + col0]) =
                        make_float2(acc[mt][nt][2], acc[mt][nt][3]);
            }
        }
    }
}

// ---------------- bias init / relu+split / scatter / pool ----------------
__global__ void init_h1_v4(const float* __restrict__ b1) {
    unsigned i = blockIdx.x * blockDim.x + threadIdx.x;   // over NNODES*N1/4
    if (i >= (unsigned)NNODES * (N1 / 4)) return;
    unsigned i4 = i * 4;
    unsigned j = i4 % N1;
    float4 bv = *reinterpret_cast<const float4*>(&b1[j]);
    *reinterpret_cast<float4*>(&g_h1[i4]) = bv;
}

__global__ void scatter1(const int* __restrict__ rows, const int* __restrict__ cols,
                         const float* __restrict__ vals) {
    unsigned i = blockIdx.x * blockDim.x + threadIdx.x;
    const unsigned total = (unsigned)DIMB * NEDGES * 16;  // 16 float4 groups / edge
    if (i >= total) return;
    unsigned g  = i & 15u;
    unsigned el = i >> 4;
    unsigned d  = el / NEDGES;
    int r  = rows[el];
    int c  = cols[el];
    float v = vals[el];
    const float4 s = *reinterpret_cast<const float4*>(
        &g_sup1[(size_t)c * N1 + d * NHID + g * 4]);
    float* dst = &g_h1[(size_t)r * N1 + d * NHID + g * 4];
    red_add_v4(dst, v * s.x, v * s.y, v * s.z, v * s.w);
}

__global__ void relu_split_h1() {
    unsigned i2 = blockIdx.x * blockDim.x + threadIdx.x;  // over NNODES*N1/2
    if (i2 >= (unsigned)NNODES * (N1 / 2)) return;
    unsigned i = i2 * 2;
    float2 v = *reinterpret_cast<const float2*>(&g_h1[i]);
    v.x = fmaxf(v.x, 0.f); v.y = fmaxf(v.y, 0.f);
    __nv_bfloat16 h0, l0, h1v, l1;
    split2(v.x, h0, l0);
    split2(v.y, h1v, l1);
    __nv_bfloat162 hh; hh.x = h0; hh.y = h1v;
    __nv_bfloat162 ll; ll.x = l0; ll.y = l1;
    *reinterpret_cast<__nv_bfloat162*>(&g_h1h[i]) = hh;
    *reinterpret_cast<__nv_bfloat162*>(&g_h1l[i]) = ll;
}

__global__ void init_acc2_v2(const float* __restrict__ b2) {
    unsigned i2 = blockIdx.x * blockDim.x + threadIdx.x;  // over NNODES*625
    if (i2 >= (unsigned)NNODES * (N2R / 2)) return;
    unsigned n = i2 / (N2R / 2);
    unsigned jj = (i2 - n * (N2R / 2)) * 2;
    float2 bv = *reinterpret_cast<const float2*>(&b2[jj]);
    *reinterpret_cast<float2*>(&g_acc2[(size_t)n * N2 + jj]) = bv;
}

__global__ void scatter2(const int* __restrict__ rows, const int* __restrict__ cols,
                         const float* __restrict__ vals) {
    unsigned i = blockIdx.x * blockDim.x + threadIdx.x;
    const unsigned total = (unsigned)DIMB * NEDGES * 32;  // 25 float2 groups, padded to 32
    if (i >= total) return;
    unsigned g = i & 31u;
    if (g >= 25u) return;
    unsigned el = i >> 5;
    unsigned d  = el / NEDGES;
    int r  = rows[el];
    int c  = cols[el];
    float v = vals[el];
    const float2 s = *reinterpret_cast<const float2*>(
        &g_sup2[(size_t)c * N2 + d * NCLASS + g * 2]);
    red_add_v2(&g_acc2[(size_t)r * N2 + d * NCLASS + g * 2], v * s.x, v * s.y);
}

__global__ void maxpool(float* __restrict__ out) {
    int i = blockIdx.x * blockDim.x + threadIdx.x;   // over NNODES*NCLASS
    if (i >= NNODES * NCLASS) return;
    int n = i / NCLASS, c = i - n * NCLASS;
    float m = 0.f;                                   // relu floor
    #pragma unroll
    for (int d = 0; d < DIMB; d++)
        m = fmaxf(m, g_acc2[(size_t)n * N2 + d * NCLASS + c]);
    out[i] = m;
}

// ---------------- launch ----------------
extern "C" void kernel_launch(void* const* d_in, const int* in_sizes, int n_in,
                              void* d_out, int out_size) {
    const float* x    = (const float*)d_in[0];
    const int*   rows = (const int*)  d_in[1];
    const int*   cols = (const int*)  d_in[2];
    const float* vals = (const float*)d_in[3];
    const float* W1   = (const float*)d_in[4];
    const float* b1   = (const float*)d_in[5];
    const float* W2   = (const float*)d_in[6];
    const float* b2   = (const float*)d_in[7];
    float* out = (float*)d_out;

    __nv_bfloat16 *xh, *xl, *w1h, *w1l, *h1h, *h1l, *w2h, *w2l;
    float *sup1, *sup2;
    cudaGetSymbolAddress((void**)&xh,  g_xh);
    cudaGetSymbolAddress((void**)&xl,  g_xl);
    cudaGetSymbolAddress((void**)&w1h, g_W1h);
    cudaGetSymbolAddress((void**)&w1l, g_W1l);
    cudaGetSymbolAddress((void**)&h1h, g_h1h);
    cudaGetSymbolAddress((void**)&h1l, g_h1l);
    cudaGetSymbolAddress((void**)&w2h, g_W2h);
    cudaGetSymbolAddress((void**)&w2l, g_W2l);
    cudaGetSymbolAddress((void**)&sup1, g_sup1);
    cudaGetSymbolAddress((void**)&sup2, g_sup2);

    // splits / repacks
    split_x<<<(NNODES * K1 + 255) / 256, 256>>>(x);
    repack_split_w1<<<(K1 * N1 + 255) / 256, 256>>>(W1);
    repack_split_w2<<<(K2 * N2R + 255) / 256, 256>>>(W2);

    // layer 1: sup1 = x @ W1cat  (tensor-core, bf16-split)
    {
        dim3 g((N1 + 127) / 128, (NNODES + 127) / 128);
        mma_gemm<<<g, 256>>>(xh, xl, w1h, w1l, sup1, NNODES, N1, K1P);
    }

    // h1 = relu(spmm(sup1) + b1), then split for GEMM2
    {
        unsigned tot4 = (unsigned)NNODES * (N1 / 4);
        init_h1_v4<<<(tot4 + 255) / 256, 256>>>(b1);
        unsigned stot = (unsigned)DIMB * NEDGES * 16;
        scatter1<<<(stot + 255) / 256, 256>>>(rows, cols, vals);
        unsigned tot2 = (unsigned)NNODES * (N1 / 2);
        relu_split_h1<<<(tot2 + 255) / 256, 256>>>();
    }

    // layer 2: sup2 = h1cat @ W2cat  (tensor-core, bf16-split)
    {
        dim3 g((N2 + 127) / 128, (NNODES + 127) / 128);
        mma_gemm<<<g, 256>>>(h1h, h1l, w2h, w2l, sup2, NNODES, N2, K2);
    }

    // acc2 = spmm(sup2) + b2 ; out = max_d relu(acc2)
    {
        unsigned tot2 = (unsigned)NNODES * (N2R / 2);
        init_acc2_v2<<<(tot2 + 255) / 256, 256>>>(b2);
        unsigned stot = (unsigned)DIMB * NEDGES * 32;
        scatter2<<<(stot + 255) / 256, 256>>>(rows, cols, vals);
        maxpool<<<(NNODES * NCLASS + 255) / 256, 256>>>(out);
    }
}

// round 17
// speedup vs baseline: 2.9179x; 1.5450x over previous
#include <cuda_runtime.h>
#include <cuda_bf16.h>

#define DIMB    25
#define NNODES  20000
#define NEDGES  320000
#define NFEAT   300
#define NHID    64
#define NCLASS  50

#define K1   NFEAT            // 300
#define K1P  320              // K1 padded to multiple of 32
#define N1   (DIMB*NHID)      // 1600
#define K2   N1               // 1600
#define N2R  (DIMB*NCLASS)    // 1250 (real)
#define N2   1280             // padded to multiple of 128

#define NBINS   (DIMB*NNODES)     // 500000 (d,row) bins
#define NE_TOT  (DIMB*NEDGES)     // 8M edges
#define SCAN_BLK 1024
#define NBLK_SCAN ((NBINS + SCAN_BLK - 1) / SCAN_BLK)   // 489

// ---------------- scratch (device globals; zero-initialized bss) ----------------
__device__ float g_sup1[(size_t)NNODES * N1];
__device__ float g_sup2[(size_t)NNODES * N2];
__device__ float g_acc2[(size_t)NNODES * N2];

__device__ __nv_bfloat16 g_xh[(size_t)NNODES * K1P];
__device__ __nv_bfloat16 g_xl[(size_t)NNODES * K1P];
__device__ __nv_bfloat16 g_W1h[K1P * N1];
__device__ __nv_bfloat16 g_W1l[K1P * N1];
__device__ __nv_bfloat16 g_h1h[(size_t)NNODES * K2];
__device__ __nv_bfloat16 g_h1l[(size_t)NNODES * K2];
__device__ __nv_bfloat16 g_W2h[K2 * N2];
__device__ __nv_bfloat16 g_W2l[K2 * N2];

// CSR build state
__device__ int  g_binCnt[NBINS];
__device__ int  g_binOff[NBINS];
__device__ int  g_cursor[NBINS];
__device__ int  g_blkSums[NBLK_SCAN];
__device__ int2 g_epack[(size_t)NE_TOT];   // {col, float_as_int(val)} sorted by (d,row)

// ---------------- mma helpers ----------------
__device__ __forceinline__ unsigned su32(const void* p) {
    return (unsigned)__cvta_generic_to_shared(p);
}
__device__ __forceinline__ void ldsm4(unsigned a, unsigned r[4]) {
    asm volatile("ldmatrix.sync.aligned.m8n8.x4.shared.b16 {%0,%1,%2,%3},[%4];"
                 : "=r"(r[0]), "=r"(r[1]), "=r"(r[2]), "=r"(r[3]) : "r"(a));
}
__device__ __forceinline__ void ldsm4t(unsigned a, unsigned r[4]) {
    asm volatile("ldmatrix.sync.aligned.m8n8.x4.trans.shared.b16 {%0,%1,%2,%3},[%4];"
                 : "=r"(r[0]), "=r"(r[1]), "=r"(r[2]), "=r"(r[3]) : "r"(a));
}
__device__ __forceinline__ void mma16816(float d[4], const unsigned a[4],
                                         unsigned b0, unsigned b1) {
    asm volatile(
        "mma.sync.aligned.m16n8k16.row.col.f32.bf16.bf16.f32 "
        "{%0,%1,%2,%3},{%4,%5,%6,%7},{%8,%9},{%0,%1,%2,%3};"
        : "+f"(d[0]), "+f"(d[1]), "+f"(d[2]), "+f"(d[3])
        : "r"(a[0]), "r"(a[1]), "r"(a[2]), "r"(a[3]), "r"(b0), "r"(b1));
}
__device__ __forceinline__ void split2(float v, __nv_bfloat16& h, __nv_bfloat16& l) {
    h = __float2bfloat16(v);
    l = __float2bfloat16(v - __bfloat162float(h));
}

// ---------------- split / repack kernels ----------------
__global__ void split_x(const float* __restrict__ x) {
    int i = blockIdx.x * blockDim.x + threadIdx.x;
    if (i >= NNODES * K1) return;
    int n = i / K1, f = i - n * K1;
    __nv_bfloat16 h, l;
    split2(x[i], h, l);
    g_xh[(size_t)n * K1P + f] = h;
    g_xl[(size_t)n * K1P + f] = l;
}

__global__ void repack_split_w1(const float* __restrict__ W1) {
    int i = blockIdx.x * blockDim.x + threadIdx.x;
    if (i >= K1 * N1) return;
    int f = i / N1, j = i - f * N1;
    int d = j >> 6, h = j & 63;
    __nv_bfloat16 bh, bl;
    split2(W1[((size_t)d * NFEAT + f) * NHID + h], bh, bl);
    g_W1h[i] = bh;
    g_W1l[i] = bl;
}

__global__ void repack_split_w2(const float* __restrict__ W2) {
    int i = blockIdx.x * blockDim.x + threadIdx.x;
    if (i >= K2 * N2R) return;
    int k = i / N2R, j = i - k * N2R;
    int d = j / NCLASS, c = j - d * NCLASS;
    __nv_bfloat16 bh, bl;
    split2(W2[((size_t)d * K2 + k) * NCLASS + c], bh, bl);
    g_W2h[(size_t)k * N2 + j] = bh;
    g_W2l[(size_t)k * N2 + j] = bl;
}

// ---------------- CSR build (counting sort by (d, dest_row)) ----------------
__global__ void csr_zero() {
    int i = blockIdx.x * blockDim.x + threadIdx.x;
    if (i < NBINS) g_binCnt[i] = 0;
}

__global__ void csr_hist(const int* __restrict__ rows) {
    int i = blockIdx.x * blockDim.x + threadIdx.x;
    if (i >= NE_TOT) return;
    int d = i / NEDGES;
    atomicAdd(&g_binCnt[d * NNODES + rows[i]], 1);
}

__global__ void csr_scan1() {   // per-block exclusive scan; block totals out
    __shared__ int s[SCAN_BLK];
    int t = threadIdx.x;
    int idx = blockIdx.x * SCAN_BLK + t;
    int v = (idx < NBINS) ? g_binCnt[idx] : 0;
    s[t] = v;
    __syncthreads();
    for (int off = 1; off < SCAN_BLK; off <<= 1) {
        int x = 0;
        if (t >= off) x = s[t - off];
        __syncthreads();
        if (t >= off) s[t] += x;
        __syncthreads();
    }
    if (idx < NBINS) g_binOff[idx] = s[t] - v;          // exclusive
    if (t == SCAN_BLK - 1) g_blkSums[blockIdx.x] = s[t]; // inclusive total
}

__global__ void csr_scan2() {   // single block, exclusive scan of block sums
    __shared__ int s[512];
    int t = threadIdx.x;
    int v = (t < NBLK_SCAN) ? g_blkSums[t] : 0;
    s[t] = v;
    __syncthreads();
    for (int off = 1; off < 512; off <<= 1) {
        int x = 0;
        if (t >= off) x = s[t - off];
        __syncthreads();
        if (t >= off) s[t] += x;
        __syncthreads();
    }
    if (t < NBLK_SCAN) g_blkSums[t] = s[t] - v;         // exclusive
}

__global__ void csr_scan3() {   // add block offsets; init cursors
    int i = blockIdx.x * blockDim.x + threadIdx.x;
    if (i >= NBINS) return;
    int o = g_binOff[i] + g_blkSums[i / SCAN_BLK];
    g_binOff[i] = o;
    g_cursor[i] = o;
}

__global__ void csr_place(const int* __restrict__ rows, const int* __restrict__ cols,
                          const float* __restrict__ vals) {
    int i = blockIdx.x * blockDim.x + threadIdx.x;
    if (i >= NE_TOT) return;
    int d = i / NEDGES;
    int bin = d * NNODES + rows[i];
    int pos = atomicAdd(&g_cursor[bin], 1);
    g_epack[pos] = make_int2(cols[i], __float_as_int(vals[i]));
}

// ---------------- gather-spmm layer 1: h1h/h1l = split(relu(A@sup1 + b1)) ----
// one warp per (d,row) bin; lane owns 2 of 64 features
__global__ __launch_bounds__(256) void gather1(const float* __restrict__ b1) {
    int gw = (blockIdx.x * 256 + threadIdx.x) >> 5;
    if (gw >= NBINS) return;
    int lane = threadIdx.x & 31;
    int d = gw / NNODES;
    int r = gw - d * NNODES;
    int start = g_binOff[gw];
    int n = g_binCnt[gw];
    int fo = d * NHID + lane * 2;

    float ax = 0.f, ay = 0.f;
    for (int i = 0; i < n; i++) {
        int2 e = g_epack[start + i];                 // broadcast
        float v = __int_as_float(e.y);
        const float2 s = *reinterpret_cast<const float2*>(
            &g_sup1[(size_t)e.x * N1 + fo]);
        ax = fmaf(v, s.x, ax);
        ay = fmaf(v, s.y, ay);
    }
    const float2 bb = *reinterpret_cast<const float2*>(&b1[fo]);
    ax = fmaxf(ax + bb.x, 0.f);
    ay = fmaxf(ay + bb.y, 0.f);

    __nv_bfloat16 h0, l0, h1v, l1;
    split2(ax, h0, l0);
    split2(ay, h1v, l1);
    __nv_bfloat162 hh; hh.x = h0; hh.y = h1v;
    __nv_bfloat162 ll; ll.x = l0; ll.y = l1;
    size_t o = (size_t)r * K2 + fo;
    *reinterpret_cast<__nv_bfloat162*>(&g_h1h[o]) = hh;
    *reinterpret_cast<__nv_bfloat162*>(&g_h1l[o]) = ll;
}

// ---------------- gather-spmm layer 2: acc2 = A@sup2 + b2 ----
// one warp per (d,row) bin; lanes 0..24 own 2 of 50 features
__global__ __launch_bounds__(256) void gather2(const float* __restrict__ b2) {
    int gw = (blockIdx.x * 256 + threadIdx.x) >> 5;
    if (gw >= NBINS) return;
    int lane = threadIdx.x & 31;
    if (lane >= 25) return;
    int d = gw / NNODES;
    int r = gw - d * NNODES;
    int start = g_binOff[gw];
    int n = g_binCnt[gw];
    int co = d * NCLASS + lane * 2;

    float ax = 0.f, ay = 0.f;
    for (int i = 0; i < n; i++) {
        int2 e = g_epack[start + i];
        float v = __int_as_float(e.y);
        const float2 s = *reinterpret_cast<const float2*>(
            &g_sup2[(size_t)e.x * N2 + co]);
        ax = fmaf(v, s.x, ax);
        ay = fmaf(v, s.y, ay);
    }
    const float2 bb = *reinterpret_cast<const float2*>(&b2[co]);
    *reinterpret_cast<float2*>(&g_acc2[(size_t)r * N2 + co]) =
        make_float2(ax + bb.x, ay + bb.y);
}

// ---------------- bf16-split tensor-core GEMM (measured 60% tensor) ----
__global__ __launch_bounds__(256) void mma_gemm(
    const __nv_bfloat16* __restrict__ Ah, const __nv_bfloat16* __restrict__ Al,
    const __nv_bfloat16* __restrict__ Bh, const __nv_bfloat16* __restrict__ Bl,
    float* __restrict__ C, int M, int N, int K)
{
    __shared__ __align__(16) __nv_bfloat16 As[2][128][40];
    __shared__ __align__(16) __nv_bfloat16 Bs[2][32][136];

    const int tid  = threadIdx.x;
    const int lane = tid & 31;
    const int wid  = tid >> 5;
    const int wm   = wid >> 1;
    const int wn   = wid & 1;
    const int rowBase = blockIdx.y * 128;
    const int colBase = blockIdx.x * 128;

    float acc[2][8][4];
    #pragma unroll
    for (int a = 0; a < 2; a++)
        #pragma unroll
        for (int b = 0; b < 8; b++)
            #pragma unroll
            for (int c = 0; c < 4; c++) acc[a][b][c] = 0.f;

    const int ar = tid >> 2;
    const int aseg = (tid & 3) * 8;
    const int br = tid >> 4;
    const int bseg = (tid & 15) * 8;

    for (int k0 = 0; k0 < K; k0 += 32) {
        #pragma unroll
        for (int rr = 0; rr < 2; rr++) {
            int r = ar + rr * 64;
            int gr = rowBase + r;
            uint4 vh = make_uint4(0, 0, 0, 0), vl = make_uint4(0, 0, 0, 0);
            if (gr < M) {
                vh = *reinterpret_cast<const uint4*>(&Ah[(size_t)gr * K + k0 + aseg]);
                vl = *reinterpret_cast<const uint4*>(&Al[(size_t)gr * K + k0 + aseg]);
            }
            *reinterpret_cast<uint4*>(&As[0][r][aseg]) = vh;
            *reinterpret_cast<uint4*>(&As[1][r][aseg]) = vl;
        }
        #pragma unroll
        for (int rr = 0; rr < 2; rr++) {
            int r = br + rr * 16;
            int gc = colBase + bseg;
            uint4 vh = make_uint4(0, 0, 0, 0), vl = make_uint4(0, 0, 0, 0);
            if (gc < N) {
                vh = *reinterpret_cast<const uint4*>(&Bh[(size_t)(k0 + r) * N + gc]);
                vl = *reinterpret_cast<const uint4*>(&Bl[(size_t)(k0 + r) * N + gc]);
            }
            *reinterpret_cast<uint4*>(&Bs[0][r][bseg]) = vh;
            *reinterpret_cast<uint4*>(&Bs[1][r][bseg]) = vl;
        }
        __syncthreads();

        #pragma unroll
        for (int ks = 0; ks < 2; ks++) {
            const int kl = ks * 16;
            unsigned ah[2][4], al[2][4];
            #pragma unroll
            for (int mt = 0; mt < 2; mt++) {
                int rowS = wm * 32 + mt * 16 + (lane & 15);
                int colS = kl + (lane >> 4) * 8;
                ldsm4(su32(&As[0][rowS][colS]), ah[mt]);
                ldsm4(su32(&As[1][rowS][colS]), al[mt]);
            }
            unsigned bh[4][4], bl[4][4];
            #pragma unroll
            for (int t = 0; t < 4; t++) {
                int rowS = kl + ((lane >> 3) & 1) * 8 + (lane & 7);
                int colS = wn * 64 + t * 16 + (lane >> 4) * 8;
                ldsm4t(su32(&Bs[0][rowS][colS]), bh[t]);
                ldsm4t(su32(&Bs[1][rowS][colS]), bl[t]);
            }
            #pragma unroll
            for (int mt = 0; mt < 2; mt++)
                #pragma unroll
                for (int nt = 0; nt < 8; nt++) {
                    int t = nt >> 1, p = (nt & 1) * 2;
                    mma16816(acc[mt][nt], ah[mt], bh[t][p], bh[t][p + 1]);
                    mma16816(acc[mt][nt], ah[mt], bl[t][p], bl[t][p + 1]);
                    mma16816(acc[mt][nt], al[mt], bh[t][p], bh[t][p + 1]);
                }
        }
        __syncthreads();
    }

    #pragma unroll
    for (int mt = 0; mt < 2; mt++) {
        #pragma unroll
        for (int nt = 0; nt < 8; nt++) {
            int row0 = rowBase + wm * 32 + mt * 16 + (lane >> 2);
            int col0 = colBase + wn * 64 + nt * 8 + (lane & 3) * 2;
            if (col0 < N) {
                if (row0 < M)
                    *reinterpret_cast<float2*>(&C[(size_t)row0 * N + col0]) =
                        make_float2(acc[mt][nt][0], acc[mt][nt][1]);
                if (row0 + 8 < M)
                    *reinterpret_cast<float2*>(&C[(size_t)(row0 + 8) * N + col0]) =
                        make_float2(acc[mt][nt][2], acc[mt][nt][3]);
            }
        }
    }
}

// ---------------- maxpool ----------------
__global__ void maxpool(float* __restrict__ out) {
    int i = blockIdx.x * blockDim.x + threadIdx.x;
    if (i >= NNODES * NCLASS) return;
    int n = i / NCLASS, c = i - n * NCLASS;
    float m = 0.f;                                   // relu floor
    #pragma unroll
    for (int d = 0; d < DIMB; d++)
        m = fmaxf(m, g_acc2[(size_t)n * N2 + d * NCLASS + c]);
    out[i] = m;
}

// ---------------- launch ----------------
extern "C" void kernel_launch(void* const* d_in, const int* in_sizes, int n_in,
                              void* d_out, int out_size) {
    const float* x    = (const float*)d_in[0];
    const int*   rows = (const int*)  d_in[1];
    const int*   cols = (const int*)  d_in[2];
    const float* vals = (const float*)d_in[3];
    const float* W1   = (const float*)d_in[4];
    const float* b1   = (const float*)d_in[5];
    const float* W2   = (const float*)d_in[6];
    const float* b2   = (const float*)d_in[7];
    float* out = (float*)d_out;

    __nv_bfloat16 *xh, *xl, *w1h, *w1l, *h1h, *h1l, *w2h, *w2l;
    float *sup1, *sup2;
    cudaGetSymbolAddress((void**)&xh,  g_xh);
    cudaGetSymbolAddress((void**)&xl,  g_xl);
    cudaGetSymbolAddress((void**)&w1h, g_W1h);
    cudaGetSymbolAddress((void**)&w1l, g_W1l);
    cudaGetSymbolAddress((void**)&h1h, g_h1h);
    cudaGetSymbolAddress((void**)&h1l, g_h1l);
    cudaGetSymbolAddress((void**)&w2h, g_W2h);
    cudaGetSymbolAddress((void**)&w2l, g_W2l);
    cudaGetSymbolAddress((void**)&sup1, g_sup1);
    cudaGetSymbolAddress((void**)&sup2, g_sup2);

    // CSR build (edge structure is reused by both gather layers)
    csr_zero<<<(NBINS + 255) / 256, 256>>>();
    csr_hist<<<(NE_TOT + 255) / 256, 256>>>(rows);
    csr_scan1<<<NBLK_SCAN, SCAN_BLK>>>();
    csr_scan2<<<1, 512>>>();
    csr_scan3<<<(NBINS + 255) / 256, 256>>>();
    csr_place<<<(NE_TOT + 255) / 256, 256>>>(rows, cols, vals);

    // splits / repacks
    split_x<<<(NNODES * K1 + 255) / 256, 256>>>(x);
    repack_split_w1<<<(K1 * N1 + 255) / 256, 256>>>(W1);
    repack_split_w2<<<(K2 * N2R + 255) / 256, 256>>>(W2);

    // layer 1: sup1 = x @ W1cat (tensor-core)
    {
        dim3 g((N1 + 127) / 128, (NNODES + 127) / 128);
        mma_gemm<<<g, 256>>>(xh, xl, w1h, w1l, sup1, NNODES, N1, K1P);
    }

    // h1 = relu(spmm(sup1) + b1) -> split, fused (one warp per bin)
    gather1<<<(NBINS * 32 + 255) / 256, 256>>>(b1);

    // layer 2: sup2 = h1cat @ W2cat (tensor-core)
    {
        dim3 g((N2 + 127) / 128, (NNODES + 127) / 128);
        mma_gemm<<<g, 256>>>(h1h, h1l, w2h, w2l, sup2, NNODES, N2, K2);
    }

    // acc2 = spmm(sup2) + b2, fused; then max-pool
    gather2<<<(NBINS * 32 + 255) / 256, 256>>>(b2);
    maxpool<<<(NNODES * NCLASS + 255) / 256, 256>>>(out);
}